// round 17
// baseline (speedup 1.0000x reference)
#include <cuda_runtime.h>
#include <math.h>
#include <stdint.h>

// ===========================================================================
// ForceFieldPredictor R17: Phase B as 4 independent 4-warp quads per CTA.
//   Quad owns a 32-row tile stream; warp = 32 rows x 32 cols (R12-proven
//   layer code, 2 MMAs per B LDS.64 -> half the crossbar bytes of R14).
//   Quad-scoped named barriers (bar.sync 1+qid, 128); 4 barriers per trunk
//   tile, 1 per joint tile; tickets parity double-buffered per quad.
//   Phase 0 (branch MLP) and scan unchanged.
// ===========================================================================

typedef unsigned long long ull;

__device__ float g_branchM[4096 * 384];     // planar: [bo][part*128 + k]
__device__ int   g_cnt[8];                  // 0:nT 1:nJ 2:tileTick 3:scanTick
                                            // 4:scanDone 5:branchDone (memset)
__device__ int   g_trunkList[262144 + 32];
__device__ int   g_jointList[262144 + 32];
__device__ float g_tFeat[(262144 + 32) * 16];
__device__ float g_jFeat[(262144 + 32) * 16];

// ---------------------------- small PTX helpers ----------------------------

__device__ __forceinline__ uint32_t f2tf32(float x) {
    uint32_t r; asm("cvt.rna.tf32.f32 %0, %1;" : "=r"(r) : "f"(x)); return r;
}
__device__ __forceinline__ float tf32f(float x) { return __uint_as_float(f2tf32(x)); }

__device__ __forceinline__ void mma8(float* d, const uint32_t* a, uint32_t b0, uint32_t b1) {
    asm volatile("mma.sync.aligned.m16n8k8.row.col.f32.tf32.tf32.f32 "
                 "{%0,%1,%2,%3}, {%4,%5,%6,%7}, {%8,%9}, {%0,%1,%2,%3};"
                 : "+f"(d[0]), "+f"(d[1]), "+f"(d[2]), "+f"(d[3])
                 : "r"(a[0]), "r"(a[1]), "r"(a[2]), "r"(a[3]), "r"(b0), "r"(b1));
}

#define BARG(id)  asm volatile("bar.sync %0, %1;" :: "r"(id), "r"(256) : "memory")
#define BARQ(id)  asm volatile("bar.sync %0, %1;" :: "r"(id), "r"(128) : "memory")

// ---------------------------- smem layout (floats) -------------------------
#define S_W1    0                 // 16384 : hidden W1 (tf32, pair-packed XOR)
#define S_W2    16384             // 16384 : hidden W2
#define S_ACT   32768             // 16896 : phase0: 2x(64x132); phaseB: 4x(32x132)
#define S_W0T   49664             // 2304 : input W0t [n][k], stride 18
#define S_JW0T  51968             // 2304 : joint W0t
#define S_B0    54272
#define S_B1    54400
#define S_B2    54528
#define S_JB0   54656
#define S_JW1   54784             // 256 : [part][128]
#define S_OUTW  55040             // 384 : out_w planar (phase 0 only)
#define S_TICK  55424             // ints: 4 quads x 2 parity + scan slot @16
#define S_TOTAL 55444

#define ASTR 132
#define WSTR 18
#define NT   512
#define GSLICE 8448               // phase-0 group act slice (64 x 132)
#define QSLICE 4224               // phase-B quad act slice (32 x 132)

// pair-packed chunk-XOR weight placement: W[n][k] ->
//   n*128 + ((k>>3) ^ (n&7))*8 + (k&3)*2 + ((k>>2)&1)
__device__ __forceinline__ int wswz(int n, int k) {
    return n * 128 + ((((k >> 3) ^ (n & 7)) << 3) + ((k & 3) << 1) + ((k >> 2) & 1));
}

// ----------------------- tf32 MMA layer helpers ----------------------------
// 32-row x 32-col warp tile (R12-proven): rows rb*16 + {g, g+8}, cols wc*32+nt*8.

template<int C>
__device__ __forceinline__ void layer_input_regs(const float* __restrict__ sWin,
                                                 const uint32_t A[][2][4],
                                                 float (*d)[4], int wc, int g, int t4)
{
    #pragma unroll
    for (int i = 0; i < 8; i++)
        d[i][0] = d[i][1] = d[i][2] = d[i][3] = 0.f;
    const float* b0p = sWin + (wc * 32 + g) * WSTR + t4;
    #pragma unroll
    for (int c = 0; c < C; c++) {
        #pragma unroll
        for (int nt = 0; nt < 4; nt++) {
            const float* bp = b0p + nt * 8 * WSTR + c * 8;
            uint32_t b0 = __float_as_uint(bp[0]);
            uint32_t b1 = __float_as_uint(bp[4]);
            mma8(d[nt],     A[c][0], b0, b1);
            mma8(d[4 + nt], A[c][1], b0, b1);
        }
    }
}

// act is a 32-row slice (rows 0..31)
__device__ __forceinline__ void hidden32(const float* __restrict__ sW,
                                         const float* __restrict__ act,
                                         float (*d)[4], int wc, int g, int t4)
{
    #pragma unroll
    for (int i = 0; i < 8; i++)
        d[i][0] = d[i][1] = d[i][2] = d[i][3] = 0.f;
    const float* a0p = act + g * ASTR + t4;
    const float* b0p = sW + (wc * 32 + g) * 128;
    #pragma unroll 4
    for (int c = 0; c < 16; c++) {
        uint32_t A[2][4];
        #pragma unroll
        for (int rb = 0; rb < 2; rb++) {
            const float* ap = a0p + rb * 16 * ASTR + c * 8;
            A[rb][0] = __float_as_uint(ap[0]);
            A[rb][1] = __float_as_uint(ap[8 * ASTR]);
            A[rb][2] = __float_as_uint(ap[4]);
            A[rb][3] = __float_as_uint(ap[8 * ASTR + 4]);
        }
        const int coff = ((c ^ g) << 3) + (t4 << 1);
        #pragma unroll
        for (int nt = 0; nt < 4; nt++) {
            float2 b = *(const float2*)(b0p + nt * 1024 + coff);
            uint32_t b0 = __float_as_uint(b.x);
            uint32_t b1 = __float_as_uint(b.y);
            mma8(d[nt],     A[0], b0, b1);
            mma8(d[4 + nt], A[1], b0, b1);
        }
    }
}

__device__ __forceinline__ void wb32(float (*d)[4], float* __restrict__ act,
                                     const float* __restrict__ bias,
                                     int wc, int g, int t4)
{
    #pragma unroll
    for (int rb = 0; rb < 2; rb++) {
        const int r = rb * 16 + g;
        #pragma unroll
        for (int nt = 0; nt < 4; nt++) {
            const int col = wc * 32 + nt * 8 + t4 * 2;
            float2 bb = *(const float2*)(bias + col);
            float* p = act + r * ASTR + col;
            const float* dd = d[rb * 4 + nt];
            p[0] = tf32f(fmaxf(dd[0] + bb.x, 0.f));
            p[1] = tf32f(fmaxf(dd[1] + bb.y, 0.f));
            p[8 * ASTR]     = tf32f(fmaxf(dd[2] + bb.x, 0.f));
            p[8 * ASTR + 1] = tf32f(fmaxf(dd[3] + bb.y, 0.f));
        }
    }
}

// -------- phase-0 group helpers (8-warp, 64-row tile; as R14) --------------

__device__ __forceinline__ void layer_hidden0(const float* __restrict__ sW,
                                              const float* __restrict__ act,
                                              float (*d)[4],
                                              int wr, int wc, int g, int t4)
{
    #pragma unroll
    for (int i = 0; i < 8; i++)
        d[i][0] = d[i][1] = d[i][2] = d[i][3] = 0.f;
    const float* a0p = act + (wr * 32 + g) * ASTR + t4;
    const float* b0p = sW + (wc * 32 + g) * 128;
    #pragma unroll 4
    for (int c = 0; c < 16; c++) {
        uint32_t A[2][4];
        #pragma unroll
        for (int rb = 0; rb < 2; rb++) {
            const float* ap = a0p + rb * 16 * ASTR + c * 8;
            A[rb][0] = __float_as_uint(ap[0]);
            A[rb][1] = __float_as_uint(ap[8 * ASTR]);
            A[rb][2] = __float_as_uint(ap[4]);
            A[rb][3] = __float_as_uint(ap[8 * ASTR + 4]);
        }
        const int coff = ((c ^ g) << 3) + (t4 << 1);
        #pragma unroll
        for (int nt = 0; nt < 4; nt++) {
            float2 b = *(const float2*)(b0p + nt * 1024 + coff);
            uint32_t b0 = __float_as_uint(b.x);
            uint32_t b1 = __float_as_uint(b.y);
            mma8(d[nt],     A[0], b0, b1);
            mma8(d[4 + nt], A[1], b0, b1);
        }
    }
}

__device__ __forceinline__ void writeback0(float (*d)[4], float* __restrict__ act,
                                           const float* __restrict__ bias,
                                           int wr, int wc, int g, int t4)
{
    #pragma unroll
    for (int rb = 0; rb < 2; rb++) {
        const int r = wr * 32 + rb * 16 + g;
        #pragma unroll
        for (int nt = 0; nt < 4; nt++) {
            const int col = wc * 32 + nt * 8 + t4 * 2;
            float2 bb = *(const float2*)(bias + col);
            float* p = act + r * ASTR + col;
            const float* dd = d[rb * 4 + nt];
            p[0] = tf32f(fmaxf(dd[0] + bb.x, 0.f));
            p[1] = tf32f(fmaxf(dd[1] + bb.y, 0.f));
            p[8 * ASTR]     = tf32f(fmaxf(dd[2] + bb.x, 0.f));
            p[8 * ASTR + 1] = tf32f(fmaxf(dd[3] + bb.y, 0.f));
        }
    }
}

// --------------------------- row feature computation -----------------------

__device__ __forceinline__ float segdist(float px, float py, float ax, float ay,
                                         float abx, float aby, float s)
{
    float t = ((px - ax) * abx + (py - ay) * aby) / s;
    t = fminf(fmaxf(t, 0.f), 1.f);
    float dx = px - (ax + t * abx);
    float dy = py - (ay + t * aby);
    return sqrtf(dx * dx + dy * dy);
}

struct RowF {
    float relx, rely, dist, maskD, maskJ, maskS;
    float i2, i3, i4, iav, i7f;
    float q2, q3, q4, qvx, qvy, qav;
};

__device__ __forceinline__ RowF rowCalc(int rowid,
    const float* __restrict__ init_x,  const float* __restrict__ query_x,
    const float* __restrict__ init_v,  const float* __restrict__ query_v,
    const float* __restrict__ init_av, const float* __restrict__ query_av)
{
    RowF f;
    const int bo = rowid >> 6, t = rowid & 63, b = rowid >> 12;
    const float* ix = init_x + bo * 9;
    const float* qx = query_x + (b * 64 + t) * 9;
    float i2 = ix[2], i3 = ix[3], i4 = ix[4], i7 = ix[7], i8 = ix[8];
    float q2 = qx[2], q3 = qx[3], q4 = qx[4], q7 = qx[7], q8 = qx[8];
    f.relx = qx[0] - ix[0]; f.rely = qx[1] - ix[1];
    f.qvx = query_v[(b * 64 + t) * 2 + 0] - init_v[bo * 2 + 0];
    f.qvy = query_v[(b * 64 + t) * 2 + 1] - init_v[bo * 2 + 1];
    f.iav = init_av[bo];
    f.qav = query_av[b * 64 + t] - f.iav;

    float sn1, cs1; sincosf(i3 * 100.f, &sn1, &cs1);
    float sn2, cs2; sincosf(q3 * 100.f, &sn2, &cs2);
    float o1x = i2 * 0.5f * cs1, o1y = i2 * 0.5f * sn1;
    float o2x = q2 * 0.5f * cs2, o2y = q2 * 0.5f * sn2;
    float ab1x = 2.f * o1x, ab1y = 2.f * o1y;
    float ab2x = 2.f * o2x, ab2y = 2.f * o2y;
    float ss1 = ab1x * ab1x + ab1y * ab1y + 1e-8f;
    float ss2 = ab2x * ab2x + ab2y * ab2y + 1e-8f;
    float A2x = f.relx - o2x, A2y = f.rely - o2y;
    float B2x = f.relx + o2x, B2y = f.rely + o2y;
    float d1 = segdist(A2x, A2y, -o1x, -o1y, ab1x, ab1y, ss1);
    float d2 = segdist(B2x, B2y, -o1x, -o1y, ab1x, ab1y, ss1);
    float d3 = segdist(-o1x, -o1y, A2x, A2y, ab2x, ab2y, ss2);
    float d4 = segdist(o1x, o1y, A2x, A2y, ab2x, ab2y, ss2);
    f.dist = fminf(fminf(d1, d2), fminf(d3, d4)) - i4 - q4;
    f.maskD = (f.dist <= 0.f) ? 1.f : 0.f;
    float ti = truncf(i7), tq = truncf(q7);
    f.maskJ = (ti == tq && i7 > 0.f) ? 1.f : 0.f;
    f.maskS = (i8 == q8 && i8 > 0.f) ? 1.f : 0.f;
    f.i2 = i2; f.i3 = i3; f.i4 = i4; f.i7f = i7 - ti;
    f.q2 = q2; f.q3 = q3; f.q4 = q4;
    return f;
}

// ------------------------------- fused kernel ------------------------------

extern "C" __global__ void __launch_bounds__(NT, 1)
ffp_all(const float* __restrict__ init_x,  const float* __restrict__ query_x,
        const float* __restrict__ init_v,  const float* __restrict__ query_v,
        const float* __restrict__ init_av, const float* __restrict__ query_av,
        const float* __restrict__ trunk_w0, const float* __restrict__ trunk_b0,
        const float* __restrict__ trunk_ws, const float* __restrict__ trunk_bs,
        const float* __restrict__ branch_w0, const float* __restrict__ branch_b0,
        const float* __restrict__ branch_ws, const float* __restrict__ branch_bs,
        const float* __restrict__ out_w,   const float* __restrict__ out_b,
        const float* __restrict__ spring_w0, const float* __restrict__ spring_b0,
        const float* __restrict__ spring_w1, const float* __restrict__ spring_b1,
        const float* __restrict__ joint_w0, const float* __restrict__ joint_b0,
        const float* __restrict__ joint_w1, const float* __restrict__ joint_b1,
        float* __restrict__ out)
{
    extern __shared__ float sm[];
    const int tid = threadIdx.x;
    const int lane = tid & 31;
    const int g = lane >> 2, t4 = lane & 3;
    // phase-0 group indices
    const int gid = tid >> 8, tg = tid & 255;
    const int wid_g = tg >> 5;
    const int wr = wid_g & 1, wcg = wid_g >> 1;
    const int barid = 1 + gid;
    int* scanT = (int*)(sm + S_TICK) + 16;

    // ================= Phase 0: branch MLP via tf32 (CTAs 0..31) ===========
    if (blockIdx.x < 32) {
        float* actg = sm + S_ACT + gid * GSLICE;
        for (int i = tid * 4; i < 2304; i += NT * 4)
            *(float4*)(sm + S_W0T + i) = make_float4(0.f, 0.f, 0.f, 0.f);
        __syncthreads();
        for (int idx = tid; idx < 16384; idx += NT) {
            int k = idx >> 7, n = idx & 127;
            int off = wswz(n, k);
            sm[S_W1 + off] = tf32f(branch_ws[idx]);
            sm[S_W2 + off] = tf32f(branch_ws[16384 + idx]);
        }
        for (int idx = tid; idx < 3 * 128; idx += NT) {
            int k = idx >> 7, n = idx & 127;
            sm[S_W0T + n * WSTR + k] = tf32f(branch_w0[(2 + k) * 128 + n]);
        }
        for (int i = tid; i < 128; i += NT) {
            sm[S_B0 + i] = branch_b0[i];
            sm[S_B1 + i] = branch_bs[i];
            sm[S_B2 + i] = branch_bs[128 + i];
        }
        for (int i = tid; i < 384; i += NT)
            sm[S_OUTW + i] = out_w[(i & 127) * 3 + (i >> 7)];
        __syncthreads();

        {
            const int boBase = (blockIdx.x * 2 + gid) * 64;
            uint32_t A[1][2][4];
            {
                const int r0 = wr * 32 + g;
                #pragma unroll
                for (int rb = 0; rb < 2; rb++) {
                    const float* ix0 = init_x + (boBase + r0 + rb * 16) * 9;
                    const float* ix8 = init_x + (boBase + r0 + rb * 16 + 8) * 9;
                    A[0][rb][0] = (t4 < 3) ? f2tf32(__ldg(ix0 + 2 + t4)) : 0u;
                    A[0][rb][1] = (t4 < 3) ? f2tf32(__ldg(ix8 + 2 + t4)) : 0u;
                    A[0][rb][2] = 0u;
                    A[0][rb][3] = 0u;
                }
            }
            float d[8][4];
            layer_input_regs<1>(sm + S_W0T, A, d, wcg, g, t4);
            writeback0(d, actg, sm + S_B0, wr, wcg, g, t4);
            BARG(barid);
            layer_hidden0(sm + S_W1, actg, d, wr, wcg, g, t4);
            BARG(barid);
            writeback0(d, actg, sm + S_B1, wr, wcg, g, t4);
            BARG(barid);
            layer_hidden0(sm + S_W2, actg, d, wr, wcg, g, t4);
            #pragma unroll
            for (int rb = 0; rb < 2; rb++) {
                const int rA = wr * 32 + rb * 16 + g;
                const int rB = rA + 8;
                #pragma unroll
                for (int nt = 0; nt < 4; nt++) {
                    const int col = wcg * 32 + nt * 8 + 2 * t4;
                    float2 bb = *(const float2*)(sm + S_B2 + col);
                    const float* dd = d[rb * 4 + nt];
                    float h0 = dd[0] + bb.x, h1 = dd[1] + bb.y;
                    float h2 = dd[2] + bb.x, h3 = dd[3] + bb.y;
                    #pragma unroll
                    for (int part = 0; part < 3; part++) {
                        float2 ow = *(const float2*)(sm + S_OUTW + part * 128 + col);
                        *(float2*)(g_branchM + (boBase + rA) * 384 + part * 128 + col)
                            = make_float2(h0 * ow.x, h1 * ow.y);
                        *(float2*)(g_branchM + (boBase + rB) * 384 + part * 128 + col)
                            = make_float2(h2 * ow.x, h3 * ow.y);
                    }
                }
            }
            BARG(barid);
            if (tg == 0) { __threadfence(); atomicAdd(&g_cnt[5], 1); }
        }
        __syncthreads();
    }

    // ---- stage trunk/joint weights (all CTAs) ----
    for (int i = tid * 4; i < 4608; i += NT * 4)
        *(float4*)(sm + S_W0T + i) = make_float4(0.f, 0.f, 0.f, 0.f);
    __syncthreads();
    for (int idx = tid; idx < 16384; idx += NT) {
        int k = idx >> 7, n = idx & 127;
        int off = wswz(n, k);
        sm[S_W1 + off] = tf32f(trunk_ws[idx]);
        sm[S_W2 + off] = tf32f(trunk_ws[16384 + idx]);
    }
    for (int idx = tid; idx < 9 * 128; idx += NT) {
        int k = idx >> 7, n = idx & 127;
        sm[S_W0T + n * WSTR + k] = tf32f(trunk_w0[idx]);
    }
    for (int idx = tid; idx < 15 * 128; idx += NT) {
        int k = idx >> 7, n = idx & 127;
        sm[S_JW0T + n * WSTR + k] = tf32f(joint_w0[idx]);
    }
    for (int i = tid; i < 128; i += NT) {
        sm[S_B0 + i]  = trunk_b0[i];
        sm[S_B1 + i]  = trunk_bs[i];
        sm[S_B2 + i]  = trunk_bs[128 + i];
        sm[S_JB0 + i] = joint_b0[i];
    }
    if (tid < 256) sm[S_JW1 + tid] = joint_w1[(tid & 127) * 2 + (tid >> 7)];
    __syncthreads();

    // ================= Scan: chunk-stolen rows =============================
    for (;;) {
        if (tid == 0) *scanT = atomicAdd(&g_cnt[3], 1);
        __syncthreads();
        const int ch = *scanT;
        __syncthreads();
        if (ch >= 128) break;
        #pragma unroll
        for (int i = 0; i < 4; i++) {
            const int rid = ch * 2048 + i * 512 + tid;
            RowF f = rowCalc(rid, init_x, query_x, init_v, query_v, init_av, query_av);
            unsigned mD = __ballot_sync(0xffffffffu, f.maskD > 0.f);
            if (mD) {
                int base = 0;
                if (lane == 0) base = atomicAdd(&g_cnt[0], __popc(mD));
                base = __shfl_sync(0xffffffffu, base, 0);
                if (f.maskD > 0.f) {
                    int pos = base + __popc(mD & ((1u << lane) - 1u));
                    g_trunkList[pos] = rid;
                    float4* fp = (float4*)(g_tFeat + pos * 16);
                    fp[0] = make_float4(tf32f(f.relx), tf32f(f.rely), tf32f(f.q2), tf32f(f.q3));
                    fp[1] = make_float4(tf32f(f.q4), tf32f(f.qvx), tf32f(f.qvy), tf32f(f.qav));
                    fp[2] = make_float4(tf32f(f.dist * 100.f), 0.f, 0.f, 0.f);
                    fp[3] = make_float4(0.f, 0.f, 0.f, 0.f);
                }
            }
            unsigned mJ = __ballot_sync(0xffffffffu, f.maskJ > 0.f);
            if (mJ) {
                int base = 0;
                if (lane == 0) base = atomicAdd(&g_cnt[1], __popc(mJ));
                base = __shfl_sync(0xffffffffu, base, 0);
                if (f.maskJ > 0.f) {
                    int pos = base + __popc(mJ & ((1u << lane) - 1u));
                    g_jointList[pos] = rid;
                    float4* fp = (float4*)(g_jFeat + pos * 16);
                    fp[0] = make_float4(0.f, 0.f, tf32f(f.i2), tf32f(f.i3));
                    fp[1] = make_float4(tf32f(f.i4), tf32f(f.relx), tf32f(f.rely), tf32f(f.q2));
                    fp[2] = make_float4(tf32f(f.q3), tf32f(f.q4), tf32f(f.qvx), tf32f(f.qvy));
                    fp[3] = make_float4(tf32f(f.iav), tf32f(f.qav), tf32f(f.i7f), 0.f);
                }
            }
            if (f.maskS > 0.f) {   // essentially never; exact scalar path
                float len = sqrtf(f.relx * f.relx + f.rely * f.rely);
                float sf = __ldg(spring_b1);
                for (int k = 0; k < 128; k++)
                    sf = fmaf(fmaxf(fmaf(len, __ldg(spring_w0 + k), __ldg(spring_b0 + k)), 0.f),
                              __ldg(spring_w1 + k), sf);
                float inv = 1.f / (len + 1e-8f);
                atomicAdd(out + rid * 3 + 0, sf * (-f.relx * inv));
                atomicAdd(out + rid * 3 + 1, sf * (-f.rely * inv));
            }
        }
        __threadfence();
        __syncthreads();
        if (tid == 0) atomicAdd(&g_cnt[4], 1);
    }

    // ---- wait for scan completion ----
    if (tid == 0) {
        while (*(volatile int*)&g_cnt[4] < 128) __nanosleep(64);
    }
    __syncthreads();
    __threadfence();
    const int nT = *(volatile int*)&g_cnt[0];
    const int nJ = *(volatile int*)&g_cnt[1];
    const int nJ32 = (nJ + 31) >> 5, nT32 = (nT + 31) >> 5;
    const int nTot = nJ32 + nT32;

    // ================= Phase B: 4 independent quad chains ===================
    const int qid = tid >> 7;               // quad 0..3
    const int wq  = (tid >> 5) & 3;         // warp-in-quad (col group)
    const int qbar = 1 + qid;
    float* qact = sm + S_ACT + qid * QSLICE;
    int* qtick = (int*)(sm + S_TICK) + qid * 2;

    if (wq == 0 && lane == 0) qtick[0] = atomicAdd(&g_cnt[2], 1);
    BARQ(qbar);
    int cp = 0;
    int cur = qtick[0];
    bool branchOK = false;

    while (cur < nTot) {
        if (wq == 0 && lane == 0) qtick[cp ^ 1] = atomicAdd(&g_cnt[2], 1);
        const bool isTrunk = (cur >= nJ32);
        const int base = (isTrunk ? (cur - nJ32) : cur) << 5;
        const int nList = isTrunk ? nT : nJ;
        const int* gL = isTrunk ? g_trunkList : g_jointList;
        const float* gF = isTrunk ? g_tFeat : g_jFeat;

        // row ids for this thread's 4 accumulator rows (rb x {g, g+8})
        int qrow[4], qrid[4];
        #pragma unroll
        for (int q = 0; q < 4; q++) {
            qrow[q] = (q >> 1) * 16 + g + (q & 1) * 8;
            const int i = base + qrow[q];
            qrid[q] = (i < nList) ? __ldg(gL + i) : -1;
        }

        // gather A fragments straight from global (position-indexed)
        uint32_t A[2][2][4];
        #pragma unroll
        for (int rb = 0; rb < 2; rb++) {
            const float* pa = gF + (base + rb * 16 + g) * 16 + t4;
            const float* pb = pa + 8 * 16;
            #pragma unroll
            for (int c = 0; c < 2; c++) {
                A[c][rb][0] = __float_as_uint(__ldg(pa + c * 8));
                A[c][rb][1] = __float_as_uint(__ldg(pb + c * 8));
                A[c][rb][2] = __float_as_uint(__ldg(pa + c * 8 + 4));
                A[c][rb][3] = __float_as_uint(__ldg(pb + c * 8 + 4));
            }
        }
        float d[8][4];
        int nxt;

        if (isTrunk) {
            layer_input_regs<2>(sm + S_W0T, A, d, wq, g, t4);
            BARQ(qbar);                 // #1: prev-tile act reads done; tick visible
            nxt = qtick[cp ^ 1];
            wb32(d, qact, sm + S_B0, wq, g, t4);
            BARQ(qbar);                 // #2
            hidden32(sm + S_W1, qact, d, wq, g, t4);
            BARQ(qbar);                 // #3
            wb32(d, qact, sm + S_B1, wq, g, t4);
            BARQ(qbar);                 // #4
            hidden32(sm + S_W2, qact, d, wq, g, t4);

            if (!branchOK) {            // gate only the epilogue
                while (*(volatile int*)&g_cnt[5] < 64) __nanosleep(32);
                __threadfence();
                branchOK = true;
            }
            int qbo[4];
            #pragma unroll
            for (int q = 0; q < 4; q++) qbo[q] = (qrid[q] >= 0) ? (qrid[q] >> 6) : 0;

            float p[4][3];
            #pragma unroll
            for (int q = 0; q < 4; q++) p[q][0] = p[q][1] = p[q][2] = 0.f;
            #pragma unroll
            for (int rb = 0; rb < 2; rb++)
            #pragma unroll
            for (int nt = 0; nt < 4; nt++) {
                const int col = wq * 32 + nt * 8 + 2 * t4;
                float2 bb = *(const float2*)(sm + S_B2 + col);
                const float* dd = d[rb * 4 + nt];
                float h0 = dd[0] + bb.x, h1 = dd[1] + bb.y;
                float h2 = dd[2] + bb.x, h3 = dd[3] + bb.y;
                const float* mA = g_branchM + qbo[rb * 2] * 384 + col;
                const float* mB = g_branchM + qbo[rb * 2 + 1] * 384 + col;
                #pragma unroll
                for (int part = 0; part < 3; part++) {
                    float2 a = __ldg((const float2*)(mA + part * 128));
                    float2 b = __ldg((const float2*)(mB + part * 128));
                    p[rb * 2][part]     += h0 * a.x + h1 * a.y;
                    p[rb * 2 + 1][part] += h2 * b.x + h3 * b.y;
                }
            }
            #pragma unroll
            for (int q = 0; q < 4; q++)
            #pragma unroll
            for (int part = 0; part < 3; part++) {
                float v = p[q][part];
                v += __shfl_xor_sync(0xffffffffu, v, 1);
                v += __shfl_xor_sync(0xffffffffu, v, 2);
                if (t4 == 0 && qrid[q] >= 0)
                    atomicAdd(out + qrid[q] * 3 + part,
                              v + (wq == 0 ? __ldg(out_b + part) : 0.f));
            }
            // next iteration's BARQ #1 orders H2 act reads vs next wb
        } else {
            layer_input_regs<2>(sm + S_JW0T, A, d, wq, g, t4);
            float pj[4][2];
            #pragma unroll
            for (int q = 0; q < 4; q++) pj[q][0] = pj[q][1] = 0.f;
            #pragma unroll
            for (int rb = 0; rb < 2; rb++)
            #pragma unroll
            for (int nt = 0; nt < 4; nt++) {
                const int col = wq * 32 + nt * 8 + 2 * t4;
                float2 jb  = *(const float2*)(sm + S_JB0 + col);
                float2 w0v = *(const float2*)(sm + S_JW1 + col);
                float2 w1v = *(const float2*)(sm + S_JW1 + 128 + col);
                const float* dd = d[rb * 4 + nt];
                float h0 = fmaxf(dd[0] + jb.x, 0.f), h1 = fmaxf(dd[1] + jb.y, 0.f);
                float h2 = fmaxf(dd[2] + jb.x, 0.f), h3 = fmaxf(dd[3] + jb.y, 0.f);
                pj[rb * 2][0]     += h0 * w0v.x + h1 * w0v.y;
                pj[rb * 2][1]     += h0 * w1v.x + h1 * w1v.y;
                pj[rb * 2 + 1][0] += h2 * w0v.x + h3 * w0v.y;
                pj[rb * 2 + 1][1] += h2 * w1v.x + h3 * w1v.y;
            }
            #pragma unroll
            for (int q = 0; q < 4; q++)
            #pragma unroll
            for (int part = 0; part < 2; part++) {
                float v = pj[q][part];
                v += __shfl_xor_sync(0xffffffffu, v, 1);
                v += __shfl_xor_sync(0xffffffffu, v, 2);
                if (t4 == 0 && qrid[q] >= 0)
                    atomicAdd(out + qrid[q] * 3 + part,
                              v + (wq == 0 ? __ldg(joint_b1 + part) : 0.f));
            }
            BARQ(qbar);                 // ticket visibility
            nxt = qtick[cp ^ 1];
        }
        cur = nxt;
        cp ^= 1;
    }
}

// ---------------------------------------------------------------------------

extern "C" void kernel_launch(void* const* d_in, const int* in_sizes, int n_in,
                              void* d_out, int out_size)
{
    const float* init_x    = (const float*)d_in[0];
    const float* query_x   = (const float*)d_in[1];
    const float* init_v    = (const float*)d_in[2];
    const float* query_v   = (const float*)d_in[3];
    const float* init_av   = (const float*)d_in[4];
    const float* query_av  = (const float*)d_in[5];
    const float* trunk_w0  = (const float*)d_in[6];
    const float* trunk_b0  = (const float*)d_in[7];
    const float* trunk_ws  = (const float*)d_in[8];
    const float* trunk_bs  = (const float*)d_in[9];
    const float* branch_w0 = (const float*)d_in[10];
    const float* branch_b0 = (const float*)d_in[11];
    const float* branch_ws = (const float*)d_in[12];
    const float* branch_bs = (const float*)d_in[13];
    const float* out_w     = (const float*)d_in[14];
    const float* out_b     = (const float*)d_in[15];
    const float* spring_w0 = (const float*)d_in[16];
    const float* spring_b0 = (const float*)d_in[17];
    const float* spring_w1 = (const float*)d_in[18];
    const float* spring_b1 = (const float*)d_in[19];
    const float* joint_w0  = (const float*)d_in[20];
    const float* joint_b0  = (const float*)d_in[21];
    const float* joint_w1  = (const float*)d_in[22];
    const float* joint_b1  = (const float*)d_in[23];
    float* out = (float*)d_out;

    int nsm = 148;
    cudaDeviceGetAttribute(&nsm, cudaDevAttrMultiProcessorCount, 0);

    void* cntPtr = nullptr;
    cudaGetSymbolAddress(&cntPtr, g_cnt);
    cudaMemsetAsync(cntPtr, 0, 8 * sizeof(int));
    cudaMemsetAsync(out, 0, (size_t)out_size * sizeof(float));

    const int smem = S_TOTAL * sizeof(float);
    cudaFuncSetAttribute(ffp_all, cudaFuncAttributeMaxDynamicSharedMemorySize, smem);

    ffp_all<<<nsm, NT, smem>>>(init_x, query_x, init_v, query_v, init_av, query_av,
                               trunk_w0, trunk_b0, trunk_ws, trunk_bs,
                               branch_w0, branch_b0, branch_ws, branch_bs,
                               out_w, out_b,
                               spring_w0, spring_b0, spring_w1, spring_b1,
                               joint_w0, joint_b0, joint_w1, joint_b1,
                               out);
}